// round 4
// baseline (speedup 1.0000x reference)
#include <cuda_runtime.h>
#include <math.h>

// Problem constants (B=2, N=8192 fixed by the dataset)
#define BB    2
#define NN    8192
#define NDWN  1024          // N / GLOBAL_STEP
#define KNN   16
#define AD    128           // ATTN_DIM
#define QKVD  384
#define DIMF  256
#define PPB   8             // points per block in fused attention
#define KTILE 2048          // ref tile for knn

// ---------------- device scratch (static: no allocation allowed) -------------
__device__ float d_qkv_l[BB*NN*QKVD];
__device__ float d_qkv_g[BB*NN*QKVD];
__device__ float d_cat  [BB*NN*2*AD];
__device__ float d_hid  [BB*NN*DIMF];
__device__ float d_kmax [BB*NDWN*AD];
__device__ float d_vmax [BB*NDWN*AD];
__device__ float d_down_xyzp[BB*NDWN*4];
__device__ int   d_idx_l  [BB*NN*KNN];
__device__ int   d_idx_inv[BB*NN*KNN];
__device__ int   d_idx_pair[BB*NDWN*KNN];
__device__ int   d_down_idx[BB*NDWN];

// ---------------- KNN: brute force, register top-16 --------------------------
// queries (B,Q,4), refs (B,R,4); out (B,Q,16). Distances follow the reference
// formula s1 - 2*dot + s2 (ties -> lower index, matching stable top_k).
__global__ void __launch_bounds__(128) knn_kernel(
    const float* __restrict__ qpts, int Q,
    const float* __restrict__ rpts, int R,
    int* __restrict__ out)
{
    __shared__ float sxs[KTILE], sys[KTILE], szs[KTILE], sss[KTILE];
    int b = blockIdx.y;
    const float* qb = qpts + (size_t)b * Q * 4;
    const float* rb = rpts + (size_t)b * R * 4;
    int qi = blockIdx.x * blockDim.x + threadIdx.x;

    float qx = 0.f, qy = 0.f, qz = 0.f, s1 = 0.f;
    if (qi < Q) {
        qx = qb[qi*4+0]; qy = qb[qi*4+1]; qz = qb[qi*4+2];
        s1 = qx*qx + qy*qy + qz*qz;
    }
    float best[KNN];
    int   bid [KNN];
#pragma unroll
    for (int t = 0; t < KNN; t++) { best[t] = 3.4e38f; bid[t] = 0; }

    for (int base = 0; base < R; base += KTILE) {
        int cnt = min(KTILE, R - base);
        __syncthreads();
        for (int t = threadIdx.x; t < cnt; t += blockDim.x) {
            const float* rp = rb + (size_t)(base + t) * 4;
            float x = rp[0], y = rp[1], z = rp[2];
            sxs[t] = x; sys[t] = y; szs[t] = z;
            sss[t] = x*x + y*y + z*z;
        }
        __syncthreads();
        if (qi < Q) {
            for (int t = 0; t < cnt; t++) {
                float dot = qx*sxs[t] + qy*sys[t] + qz*szs[t];
                float d   = s1 - 2.0f*dot + sss[t];
                if (d < best[KNN-1]) {
                    float cd = d; int ci = base + t;
#pragma unroll
                    for (int s = 0; s < KNN; s++) {
                        if (cd < best[s]) {
                            float td = best[s]; int ti = bid[s];
                            best[s] = cd; bid[s] = ci;
                            cd = td; ci = ti;
                        }
                    }
                }
            }
        }
    }
    if (qi < Q) {
        int* op = out + ((size_t)b * Q + qi) * KNN;
#pragma unroll
        for (int t = 0; t < KNN; t++) op[t] = bid[t];
    }
}

// ---------------- FPS: one block per batch, sequential argmax ----------------
__global__ void __launch_bounds__(1024) fps_kernel(const float* __restrict__ xyzp)
{
    extern __shared__ float sm[];
    float* sx   = sm;
    float* sy   = sm + NN;
    float* sz   = sm + 2*NN;
    float* smin = sm + 3*NN;
    __shared__ float rv[32];
    __shared__ int   ri[32];
    __shared__ int   sel;

    int b = blockIdx.x;
    const float* xb = xyzp + (size_t)b * NN * 4;
    int tid = threadIdx.x;

    float x0 = xb[0], y0 = xb[1], z0 = xb[2];
    for (int i = tid; i < NN; i += 1024) {
        float x = xb[i*4+0], y = xb[i*4+1], z = xb[i*4+2];
        sx[i] = x; sy[i] = y; sz[i] = z;
        float dx = x - x0, dy = y - y0, dz = z - z0;
        smin[i] = dx*dx + dy*dy + dz*dz;
    }
    if (tid == 0) d_down_idx[b*NDWN] = 0;
    __syncthreads();

    for (int s = 1; s < NDWN; s++) {
        float bv = -1.f; int bi = NN;
        for (int i = tid; i < NN; i += 1024) {
            float v = smin[i];
            if (v > bv) { bv = v; bi = i; }   // ascending i: strict > keeps first
        }
#pragma unroll
        for (int off = 16; off; off >>= 1) {
            float ov = __shfl_down_sync(0xffffffffu, bv, off);
            int   oi = __shfl_down_sync(0xffffffffu, bi, off);
            if (ov > bv || (ov == bv && oi < bi)) { bv = ov; bi = oi; }
        }
        if ((tid & 31) == 0) { rv[tid >> 5] = bv; ri[tid >> 5] = bi; }
        __syncthreads();
        if (tid < 32) {
            bv = rv[tid]; bi = ri[tid];
#pragma unroll
            for (int off = 16; off; off >>= 1) {
                float ov = __shfl_down_sync(0xffffffffu, bv, off);
                int   oi = __shfl_down_sync(0xffffffffu, bi, off);
                if (ov > bv || (ov == bv && oi < bi)) { bv = ov; bi = oi; }
            }
            if (tid == 0) { sel = bi; d_down_idx[b*NDWN + s] = bi; }
        }
        __syncthreads();
        int p = sel;
        float px = sx[p], py = sy[p], pz = sz[p];
        for (int i = tid; i < NN; i += 1024) {
            float dx = sx[i]-px, dy = sy[i]-py, dz = sz[i]-pz;
            float d = dx*dx + dy*dy + dz*dz;
            smin[i] = fminf(smin[i], d);
        }
        __syncthreads();
    }
}

// ---------------- gather downsampled points ----------------------------------
__global__ void gather_down_kernel(const float* __restrict__ xyzp)
{
    int t = blockIdx.x * blockDim.x + threadIdx.x;
    if (t < BB*NDWN) {
        int b = t / NDWN;
        int id = d_down_idx[t];
        const float* src = xyzp + ((size_t)b * NN + id) * 4;
        float* dst = d_down_xyzp + (size_t)t * 4;
        dst[0]=src[0]; dst[1]=src[1]; dst[2]=src[2]; dst[3]=src[3];
    }
}

// ---------------- fp32 tiled GEMM: C = A@W + bias (optional relu) ------------
// BM=BN=128, BK=16, 256 threads, 8x8 microtile. M%128==0, N%128==0, K%16==0.
template<bool RELU>
__global__ void __launch_bounds__(256) gemm_kernel(
    const float* __restrict__ A, const float* __restrict__ W,
    const float* __restrict__ bias, float* __restrict__ C,
    int M, int K, int Nc)
{
    __shared__ float As[16][132];
    __shared__ float Ws[16][128];
    int bm = blockIdx.y * 128, bn = blockIdx.x * 128;
    int tid = threadIdx.x;
    int tm = (tid / 16) * 8, tn = (tid % 16) * 8;

    float acc[8][8];
#pragma unroll
    for (int i = 0; i < 8; i++)
#pragma unroll
        for (int j = 0; j < 8; j++) acc[i][j] = 0.f;

    for (int k0 = 0; k0 < K; k0 += 16) {
#pragma unroll
        for (int t = tid; t < 512; t += 256) {       // A: 128x16, float4
            int m = t >> 2, k4 = t & 3;
            float4 v = *reinterpret_cast<const float4*>(A + (size_t)(bm+m)*K + k0 + k4*4);
            As[k4*4+0][m] = v.x; As[k4*4+1][m] = v.y;
            As[k4*4+2][m] = v.z; As[k4*4+3][m] = v.w;
        }
#pragma unroll
        for (int t = tid; t < 512; t += 256) {       // W: 16x128, float4
            int k = t >> 5, n4 = t & 31;
            float4 v = *reinterpret_cast<const float4*>(W + (size_t)(k0+k)*Nc + bn + n4*4);
            *reinterpret_cast<float4*>(&Ws[k][n4*4]) = v;
        }
        __syncthreads();
#pragma unroll
        for (int k = 0; k < 16; k++) {
            float a[8], w[8];
#pragma unroll
            for (int i = 0; i < 8; i++) a[i] = As[k][tm+i];
#pragma unroll
            for (int i = 0; i < 8; i++) w[i] = Ws[k][tn+i];
#pragma unroll
            for (int i = 0; i < 8; i++)
#pragma unroll
                for (int j = 0; j < 8; j++)
                    acc[i][j] = fmaf(a[i], w[j], acc[i][j]);
        }
        __syncthreads();
    }
#pragma unroll
    for (int i = 0; i < 8; i++)
#pragma unroll
        for (int j = 0; j < 8; j++) {
            float v = acc[i][j] + bias[bn+tn+j];
            if (RELU) v = fmaxf(v, 0.f);
            C[(size_t)(bm+tm+i)*Nc + bn+tn+j] = v;
        }
}

// ---------------- global branch: max-pool gathered K/V -----------------------
__global__ void __launch_bounds__(128) kvmax_kernel()
{
    int b = blockIdx.y, r = blockIdx.x, c = threadIdx.x;
    const int* pidx = d_idx_pair + ((size_t)b*NDWN + r)*KNN;
    float km = -3.4e38f, vm = -3.4e38f;
#pragma unroll
    for (int j = 0; j < KNN; j++) {
        int id = pidx[j];
        const float* row = d_qkv_g + ((size_t)b*NN + id)*QKVD;
        km = fmaxf(km, row[AD   + c]);
        vm = fmaxf(vm, row[2*AD + c]);
    }
    d_kmax[((size_t)b*NDWN + r)*AD + c] = km;
    d_vmax[((size_t)b*NDWN + r)*AD + c] = vm;
}

// ---------------- fused pos-encode + vector attention ------------------------
// One block (128 threads = 128 channels) handles PPB points. w2 cached in smem.
__global__ void __launch_bounds__(128) attn_kernel(
    const float* __restrict__ xyzp,      // (B,N,4) query positions
    const float* __restrict__ nbr_pts,   // (B,kv_rows,4) neighbor positions
    const int*  __restrict__ nidx,       // (B,N,16)
    const float* __restrict__ qsrc,      // (B,N,384), q at col 0
    const float* __restrict__ kbase,     // row = kbase + (b*kv_rows+id)*kv_stride
    const float* __restrict__ vbase,
    int kv_stride, int kv_rows,
    const float* __restrict__ pw1, const float* __restrict__ pb1,
    const float* __restrict__ pw2, const float* __restrict__ pb2,
    const float* __restrict__ fg,  const float* __restrict__ fb,
    float* __restrict__ out, int out_coloff)
{
    extern __shared__ float sm[];
    float* w2s = sm;            // 128*128
    float* hs  = sm + 16384;    // 16*128
    float* ts  = sm + 16384 + 2048; // 16*128
    __shared__ int   sidx[KNN];
    __shared__ float sx4[KNN][4];
    __shared__ float m_s[KNN], i_s[KNN];

    int b = blockIdx.y;
    int c = threadIdx.x;
    int lane = c & 31, warp = c >> 5;

    for (int t = c; t < 16384; t += 128) w2s[t] = pw2[t];
    float w1r0 = pw1[c], w1r1 = pw1[128+c], w1r2 = pw1[256+c], w1r3 = pw1[384+c];
    float b1r = pb1[c], b2r = pb2[c], gr = fg[c], br = fb[c];
    const float inv_scale = 0.08838834764831845f;   // 1/sqrt(128)
    __syncthreads();

    for (int pp = 0; pp < PPB; pp++) {
        int i = blockIdx.x * PPB + pp;
        size_t bi = (size_t)b * NN + i;

        if (c < KNN) {
            int id = nidx[bi*KNN + c];
            sidx[c] = id;
            const float* qp = xyzp + bi*4;
            const float* np = nbr_pts + ((size_t)b*kv_rows + id)*4;
            sx4[c][0] = qp[0]-np[0]; sx4[c][1] = qp[1]-np[1];
            sx4[c][2] = qp[2]-np[2]; sx4[c][3] = qp[3]-np[3];
        }
        __syncthreads();

        // h_j = relu(x_j @ w1 + b1)
#pragma unroll
        for (int j = 0; j < KNN; j++) {
            float hv = b1r + sx4[j][0]*w1r0 + sx4[j][1]*w1r1
                           + sx4[j][2]*w1r2 + sx4[j][3]*w1r3;
            hs[j*128 + c] = fmaxf(hv, 0.f);
        }
        __syncthreads();

        // pos_j[c] = h_j @ w2 + b2 : 16 accumulators across the K loop
        float pos[KNN];
#pragma unroll
        for (int j = 0; j < KNN; j++) pos[j] = b2r;
#pragma unroll 4
        for (int k = 0; k < 128; k++) {
            float w = w2s[k*128 + c];
#pragma unroll
            for (int j = 0; j < KNN; j++)
                pos[j] = fmaf(hs[j*128 + k], w, pos[j]);
        }

        float qv = qsrc[bi*QKVD + c];
        float tr[KNN], vp[KNN];
#pragma unroll
        for (int j = 0; j < KNN; j++) {
            size_t kr = ((size_t)b*kv_rows + sidx[j]) * kv_stride;
            float kv = kbase[kr + c];
            float vv = vbase[kr + c];
            tr[j] = qv - kv + pos[j];
            vp[j] = vv + pos[j];
            ts[j*128 + c] = tr[j];
        }
        __syncthreads();

        // layernorm stats per neighbor (4 j's per warp)
#pragma unroll
        for (int jj = 0; jj < 4; jj++) {
            int j = warp*4 + jj;
            float v0 = ts[j*128+lane], v1 = ts[j*128+lane+32];
            float v2 = ts[j*128+lane+64], v3 = ts[j*128+lane+96];
            float s  = v0+v1+v2+v3;
            float ss = v0*v0+v1*v1+v2*v2+v3*v3;
#pragma unroll
            for (int off = 16; off; off >>= 1) {
                s  += __shfl_xor_sync(0xffffffffu, s,  off);
                ss += __shfl_xor_sync(0xffffffffu, ss, off);
            }
            if (lane == 0) {
                float m   = s * (1.f/128.f);
                float var = ss * (1.f/128.f) - m*m;
                if (var < 0.f) var = 0.f;
                m_s[j] = m;
                i_s[j] = 1.f / sqrtf(var + 1e-5f);
            }
        }
        __syncthreads();

        // per-channel softmax over 16 neighbors, weighted sum of (v+pos)
        float a[KNN], mx = -3.4e38f;
#pragma unroll
        for (int j = 0; j < KNN; j++) {
            a[j] = ((tr[j] - m_s[j]) * i_s[j] * gr + br) * inv_scale;
            mx = fmaxf(mx, a[j]);
        }
        float se = 0.f, ov = 0.f;
#pragma unroll
        for (int j = 0; j < KNN; j++) {
            float e = expf(a[j] - mx);
            se += e;
            ov += e * vp[j];
        }
        out[bi*(2*AD) + out_coloff + c] = ov / se;
        __syncthreads();   // protect sidx/sx4/hs/ts for next point
    }
}

// ---------------- launcher ----------------------------------------------------
extern "C" void kernel_launch(void* const* d_in, const int* in_sizes, int n_in,
                              void* d_out, int out_size)
{
    const float* xyzp     = (const float*)d_in[0];
    const float* features = (const float*)d_in[1];
    const float* l_qkv_w  = (const float*)d_in[2];
    const float* l_qkv_b  = (const float*)d_in[3];
    const float* l_pe_w1  = (const float*)d_in[4];
    const float* l_pe_b1  = (const float*)d_in[5];
    const float* l_pe_w2  = (const float*)d_in[6];
    const float* l_pe_b2  = (const float*)d_in[7];
    const float* l_fc_g   = (const float*)d_in[8];
    const float* l_fc_b   = (const float*)d_in[9];
    const float* g_qkv_w  = (const float*)d_in[10];
    const float* g_qkv_b  = (const float*)d_in[11];
    const float* g_pe_w1  = (const float*)d_in[12];
    const float* g_pe_b1  = (const float*)d_in[13];
    const float* g_pe_w2  = (const float*)d_in[14];
    const float* g_pe_b2  = (const float*)d_in[15];
    const float* g_fc_g   = (const float*)d_in[16];
    const float* g_fc_b   = (const float*)d_in[17];
    const float* proj_w1  = (const float*)d_in[18];
    const float* proj_b1  = (const float*)d_in[19];
    const float* proj_w2  = (const float*)d_in[20];
    const float* proj_b2  = (const float*)d_in[21];
    float* out = (float*)d_out;

    float *qkv_l, *qkv_g, *cat_p, *hid_p, *kmax_p, *vmax_p, *dxyzp_p;
    int *idx_l, *idx_inv, *idx_pair;
    cudaGetSymbolAddress((void**)&qkv_l,   d_qkv_l);
    cudaGetSymbolAddress((void**)&qkv_g,   d_qkv_g);
    cudaGetSymbolAddress((void**)&cat_p,   d_cat);
    cudaGetSymbolAddress((void**)&hid_p,   d_hid);
    cudaGetSymbolAddress((void**)&kmax_p,  d_kmax);
    cudaGetSymbolAddress((void**)&vmax_p,  d_vmax);
    cudaGetSymbolAddress((void**)&dxyzp_p, d_down_xyzp);
    cudaGetSymbolAddress((void**)&idx_l,   d_idx_l);
    cudaGetSymbolAddress((void**)&idx_inv, d_idx_inv);
    cudaGetSymbolAddress((void**)&idx_pair,d_idx_pair);

    const int FPS_SMEM  = 4 * NN * (int)sizeof(float);     // 128 KB
    const int ATTN_SMEM = (16384 + 2048 + 2048) * (int)sizeof(float); // 80 KB
    cudaFuncSetAttribute(fps_kernel,  cudaFuncAttributeMaxDynamicSharedMemorySize, FPS_SMEM);
    cudaFuncSetAttribute(attn_kernel, cudaFuncAttributeMaxDynamicSharedMemorySize, ATTN_SMEM);

    const int M = BB * NN;   // 16384

    // 1. self-KNN (local neighborhoods)
    knn_kernel<<<dim3(NN/128, BB), 128>>>(xyzp, NN, xyzp, NN, idx_l);

    // 2. FPS downsample + gather down points
    fps_kernel<<<BB, 1024, FPS_SMEM>>>(xyzp);
    gather_down_kernel<<<(BB*NDWN + 255)/256, 256>>>(xyzp);

    // 3. cross KNNs
    knn_kernel<<<dim3(NDWN/128, BB), 128>>>(dxyzp_p, NDWN, xyzp, NN, idx_pair);
    knn_kernel<<<dim3(NN/128,  BB), 128>>>(xyzp, NN, dxyzp_p, NDWN, idx_inv);

    // 4. QKV GEMMs
    gemm_kernel<false><<<dim3(QKVD/128, M/128), 256>>>(features, l_qkv_w, l_qkv_b, qkv_l, M, DIMF, QKVD);
    gemm_kernel<false><<<dim3(QKVD/128, M/128), 256>>>(features, g_qkv_w, g_qkv_b, qkv_g, M, DIMF, QKVD);

    // 5. global branch max-pooled K/V over pair neighborhoods
    kvmax_kernel<<<dim3(NDWN, BB), 128>>>();

    // 6. fused pos-encode + attention (local writes cat[:,0:128], global [:,128:256])
    attn_kernel<<<dim3(NN/PPB, BB), 128, ATTN_SMEM>>>(
        xyzp, xyzp, idx_l, qkv_l, qkv_l + AD, qkv_l + 2*AD, QKVD, NN,
        l_pe_w1, l_pe_b1, l_pe_w2, l_pe_b2, l_fc_g, l_fc_b, cat_p, 0);
    attn_kernel<<<dim3(NN/PPB, BB), 128, ATTN_SMEM>>>(
        xyzp, dxyzp_p, idx_inv, qkv_g, kmax_p, vmax_p, AD, NDWN,
        g_pe_w1, g_pe_b1, g_pe_w2, g_pe_b2, g_fc_g, g_fc_b, cat_p, AD);

    // 7. projection MLP
    gemm_kernel<true ><<<dim3(DIMF/128, M/128), 256>>>(cat_p, proj_w1, proj_b1, hid_p, M, 2*AD, DIMF);
    gemm_kernel<false><<<dim3(DIMF/128, M/128), 256>>>(hid_p, proj_w2, proj_b2, out,   M, DIMF, DIMF);

    (void)in_sizes; (void)n_in; (void)out_size;
}

// round 5
// speedup vs baseline: 1.2236x; 1.2236x over previous
#include <cuda_runtime.h>
#include <math.h>

#define BB    2
#define NN    8192
#define NDWN  1024
#define KNN   16
#define AD    128
#define QKVD  384
#define DIMF  256
#define PPB   8
#define KTILE 2048

// ---------------- device scratch ---------------------------------------------
__device__ float d_qkv_l[BB*NN*QKVD];
__device__ float d_qkv_g[BB*NN*QKVD];
__device__ float d_cat  [BB*NN*2*AD];
__device__ float d_hid  [BB*NN*DIMF];
__device__ float d_kmax [BB*NDWN*AD];
__device__ float d_vmax [BB*NDWN*AD];
__device__ float d_down_xyzp[BB*NDWN*4];
__device__ float d_pos  [(size_t)BB*NN*KNN*AD];   // 134 MB pos scratch (reused per branch)
__device__ int   d_idx_l  [BB*NN*KNN];
__device__ int   d_idx_inv[BB*NN*KNN];
__device__ int   d_idx_pair[BB*NDWN*KNN];
__device__ int   d_down_idx[BB*NDWN];

// ---------------- KNN: float4 smem tiles, register top-16 --------------------
__global__ void __launch_bounds__(128) knn_kernel(
    const float* __restrict__ qpts, int Q,
    const float* __restrict__ rpts, int R,
    int* __restrict__ out)
{
    __shared__ float4 sref[KTILE];          // x,y,z,|p|^2
    int b = blockIdx.y;
    const float* qb = qpts + (size_t)b * Q * 4;
    const float* rb = rpts + (size_t)b * R * 4;
    int qi = blockIdx.x * 128 + threadIdx.x;   // grids are exact multiples

    float qx = qb[qi*4+0], qy = qb[qi*4+1], qz = qb[qi*4+2];
    float s1 = qx*qx + qy*qy + qz*qz;

    float best[KNN];
    int   bid [KNN];
#pragma unroll
    for (int t = 0; t < KNN; t++) { best[t] = 3.4e38f; bid[t] = 0; }

    for (int base = 0; base < R; base += KTILE) {
        int cnt = min(KTILE, R - base);
        __syncthreads();
        for (int t = threadIdx.x; t < cnt; t += 128) {
            float4 p = *reinterpret_cast<const float4*>(rb + (size_t)(base + t) * 4);
            p.w = p.x*p.x + p.y*p.y + p.z*p.z;
            sref[t] = p;
        }
        __syncthreads();
#pragma unroll 8
        for (int t = 0; t < cnt; t++) {
            float4 p = sref[t];
            float dot = qx*p.x + qy*p.y + qz*p.z;       // same arithmetic as R3
            float d   = s1 - 2.0f*dot + p.w;
            if (d < best[KNN-1]) {
                float cd = d; int ci = base + t;
#pragma unroll
                for (int s = 0; s < KNN; s++) {
                    if (cd < best[s]) {
                        float td = best[s]; int ti = bid[s];
                        best[s] = cd; bid[s] = ci;
                        cd = td; ci = ti;
                    }
                }
            }
        }
    }
    int* op = out + ((size_t)b * Q + qi) * KNN;
#pragma unroll
    for (int t = 0; t < KNN; t++) op[t] = bid[t];
}

// ---------------- FPS: fused update+argmax pass ------------------------------
__global__ void __launch_bounds__(1024) fps_kernel(const float* __restrict__ xyzp)
{
    extern __shared__ float sm[];
    float* sx   = sm;
    float* sy   = sm + NN;
    float* sz   = sm + 2*NN;
    float* smin = sm + 3*NN;
    __shared__ float rv[32];
    __shared__ int   ri[32];
    __shared__ int   sel;

    int b = blockIdx.x, tid = threadIdx.x;
    const float* xb = xyzp + (size_t)b * NN * 4;

    float x0 = xb[0], y0 = xb[1], z0 = xb[2];
    float bv = -1.f; int bi = 0;
    for (int i = tid; i < NN; i += 1024) {
        float x = xb[i*4+0], y = xb[i*4+1], z = xb[i*4+2];
        sx[i] = x; sy[i] = y; sz[i] = z;
        float dx = x - x0, dy = y - y0, dz = z - z0;
        float d = dx*dx + dy*dy + dz*dz;
        smin[i] = d;
        if (d > bv) { bv = d; bi = i; }
    }
    if (tid == 0) d_down_idx[b*NDWN] = 0;

    for (int s = 1; s < NDWN; s++) {
#pragma unroll
        for (int off = 16; off; off >>= 1) {
            float ov = __shfl_down_sync(0xffffffffu, bv, off);
            int   oi = __shfl_down_sync(0xffffffffu, bi, off);
            if (ov > bv || (ov == bv && oi < bi)) { bv = ov; bi = oi; }
        }
        if ((tid & 31) == 0) { rv[tid >> 5] = bv; ri[tid >> 5] = bi; }
        __syncthreads();
        if (tid < 32) {
            bv = rv[tid]; bi = ri[tid];
#pragma unroll
            for (int off = 16; off; off >>= 1) {
                float ov = __shfl_down_sync(0xffffffffu, bv, off);
                int   oi = __shfl_down_sync(0xffffffffu, bi, off);
                if (ov > bv || (ov == bv && oi < bi)) { bv = ov; bi = oi; }
            }
            if (tid == 0) { sel = bi; d_down_idx[b*NDWN + s] = bi; }
        }
        __syncthreads();
        int p = sel;
        float px = sx[p], py = sy[p], pz = sz[p];
        bv = -1.f; bi = 0;
        for (int i = tid; i < NN; i += 1024) {
            float dx = sx[i]-px, dy = sy[i]-py, dz = sz[i]-pz;
            float d  = dx*dx + dy*dy + dz*dz;
            float v  = fminf(smin[i], d);
            smin[i]  = v;
            if (v > bv) { bv = v; bi = i; }
        }
        // no barrier needed: smin[i] is thread-private across passes; rv/ri
        // overwrite is fenced by the __syncthreads above next iteration.
    }
}

__global__ void gather_down_kernel(const float* __restrict__ xyzp)
{
    int t = blockIdx.x * blockDim.x + threadIdx.x;
    if (t < BB*NDWN) {
        int b = t / NDWN;
        int id = d_down_idx[t];
        const float* src = xyzp + ((size_t)b * NN + id) * 4;
        float* dst = d_down_xyzp + (size_t)t * 4;
        dst[0]=src[0]; dst[1]=src[1]; dst[2]=src[2]; dst[3]=src[3];
    }
}

// ---------------- generic fp32 tiled GEMM ------------------------------------
template<bool RELU>
__global__ void __launch_bounds__(256) gemm_kernel(
    const float* __restrict__ A, const float* __restrict__ W,
    const float* __restrict__ bias, float* __restrict__ C,
    int M, int K, int Nc)
{
    __shared__ float As[16][132];
    __shared__ float Ws[16][128];
    int bm = blockIdx.y * 128, bn = blockIdx.x * 128;
    int tid = threadIdx.x;
    int tm = (tid / 16) * 8, tn = (tid % 16) * 8;

    float acc[8][8];
#pragma unroll
    for (int i = 0; i < 8; i++)
#pragma unroll
        for (int j = 0; j < 8; j++) acc[i][j] = 0.f;

    for (int k0 = 0; k0 < K; k0 += 16) {
#pragma unroll
        for (int t = tid; t < 512; t += 256) {
            int m = t >> 2, k4 = t & 3;
            float4 v = *reinterpret_cast<const float4*>(A + (size_t)(bm+m)*K + k0 + k4*4);
            As[k4*4+0][m] = v.x; As[k4*4+1][m] = v.y;
            As[k4*4+2][m] = v.z; As[k4*4+3][m] = v.w;
        }
#pragma unroll
        for (int t = tid; t < 512; t += 256) {
            int k = t >> 5, n4 = t & 31;
            float4 v = *reinterpret_cast<const float4*>(W + (size_t)(k0+k)*Nc + bn + n4*4);
            *reinterpret_cast<float4*>(&Ws[k][n4*4]) = v;
        }
        __syncthreads();
#pragma unroll
        for (int k = 0; k < 16; k++) {
            float a[8], w[8];
#pragma unroll
            for (int i = 0; i < 8; i++) a[i] = As[k][tm+i];
#pragma unroll
            for (int i = 0; i < 8; i++) w[i] = Ws[k][tn+i];
#pragma unroll
            for (int i = 0; i < 8; i++)
#pragma unroll
                for (int j = 0; j < 8; j++)
                    acc[i][j] = fmaf(a[i], w[j], acc[i][j]);
        }
        __syncthreads();
    }
#pragma unroll
    for (int i = 0; i < 8; i++)
#pragma unroll
        for (int j = 0; j < 8; j++) {
            float v = acc[i][j] + bias[bn+tn+j];
            if (RELU) v = fmaxf(v, 0.f);
            C[(size_t)(bm+tm+i)*Nc + bn+tn+j] = v;
        }
}

// ---------------- PE GEMM: pos = relu(X@w1+b1)@w2 + b2, X generated in-block --
// Rows laid out (b, i, j): 128 rows/block = 8 points x 16 neighbors. N=128, K=128.
__global__ void __launch_bounds__(256) gemm_pe_kernel(
    const float* __restrict__ xyzp,   // (B,N,4) query positions
    const float* __restrict__ nbr,    // (B,nbr_rows,4)
    int nbr_rows,
    const int* __restrict__ nidx,     // (B,N,16)
    const float* __restrict__ w1, const float* __restrict__ b1,
    const float* __restrict__ w2, const float* __restrict__ b2,
    float* __restrict__ pos)
{
    __shared__ float As[16][132];
    __shared__ float Ws[16][128];
    __shared__ float xd[128][5];      // padded: conflict-free
    __shared__ float w1s[4][128];
    __shared__ float b1s[128];

    int bm = blockIdx.x * 128;
    int tid = threadIdx.x;

    for (int t = tid; t < 512; t += 256) w1s[t >> 7][t & 127] = w1[t];
    if (tid < 128) b1s[tid] = b1[tid];
    if (tid < 128) {
        int r  = bm + tid;
        int pi = r >> 4;               // global point index b*NN+i
        int j  = r & 15;
        int b  = pi / NN;
        int id = nidx[(size_t)pi*KNN + j];
        const float* qp = xyzp + (size_t)pi * 4;
        const float* np = nbr + ((size_t)b * nbr_rows + id) * 4;
        xd[tid][0] = qp[0]-np[0]; xd[tid][1] = qp[1]-np[1];
        xd[tid][2] = qp[2]-np[2]; xd[tid][3] = qp[3]-np[3];
    }

    int tm = (tid / 16) * 8, tn = (tid % 16) * 8;
    float acc[8][8];
#pragma unroll
    for (int i = 0; i < 8; i++)
#pragma unroll
        for (int j = 0; j < 8; j++) acc[i][j] = 0.f;

    for (int k0 = 0; k0 < 128; k0 += 16) {
        __syncthreads();
        // A tile: h[k][m] = relu(xd[m] . w1[:,k0+k] + b1[k0+k])
#pragma unroll
        for (int t = tid; t < 2048; t += 256) {
            int m = t & 127, k = t >> 7;
            int kk = k0 + k;
            float hv = b1s[kk] + xd[m][0]*w1s[0][kk] + xd[m][1]*w1s[1][kk]
                               + xd[m][2]*w1s[2][kk] + xd[m][3]*w1s[3][kk];
            As[k][m] = fmaxf(hv, 0.f);
        }
#pragma unroll
        for (int t = tid; t < 512; t += 256) {
            int k = t >> 5, n4 = t & 31;
            float4 v = *reinterpret_cast<const float4*>(w2 + (size_t)(k0+k)*128 + n4*4);
            *reinterpret_cast<float4*>(&Ws[k][n4*4]) = v;
        }
        __syncthreads();
#pragma unroll
        for (int k = 0; k < 16; k++) {
            float a[8], w[8];
#pragma unroll
            for (int i = 0; i < 8; i++) a[i] = As[k][tm+i];
#pragma unroll
            for (int i = 0; i < 8; i++) w[i] = Ws[k][tn+i];
#pragma unroll
            for (int i = 0; i < 8; i++)
#pragma unroll
                for (int j = 0; j < 8; j++)
                    acc[i][j] = fmaf(a[i], w[j], acc[i][j]);
        }
    }
#pragma unroll
    for (int i = 0; i < 8; i++)
#pragma unroll
        for (int j = 0; j < 8; j++)
            pos[(size_t)(bm+tm+i)*128 + tn+j] = acc[i][j] + b2[tn+j];
}

// ---------------- global branch: max-pool gathered K/V -----------------------
__global__ void __launch_bounds__(128) kvmax_kernel()
{
    int b = blockIdx.y, r = blockIdx.x, c = threadIdx.x;
    const int* pidx = d_idx_pair + ((size_t)b*NDWN + r)*KNN;
    float km = -3.4e38f, vm = -3.4e38f;
#pragma unroll
    for (int j = 0; j < KNN; j++) {
        int id = pidx[j];
        const float* row = d_qkv_g + ((size_t)b*NN + id)*QKVD;
        km = fmaxf(km, row[AD   + c]);
        vm = fmaxf(vm, row[2*AD + c]);
    }
    d_kmax[((size_t)b*NDWN + r)*AD + c] = km;
    d_vmax[((size_t)b*NDWN + r)*AD + c] = vm;
}

// ---------------- attention (pos precomputed) --------------------------------
__global__ void __launch_bounds__(128) attn_kernel(
    const int*  __restrict__ nidx,
    const float* __restrict__ qsrc,  int qstride,
    const float* __restrict__ kbase, const float* __restrict__ vbase,
    int kv_stride, int kv_rows,
    const float* __restrict__ pos,
    const float* __restrict__ fg,  const float* __restrict__ fb,
    float* __restrict__ out, int out_coloff)
{
    __shared__ float ts[KNN*128];
    __shared__ int   sidx[KNN];
    __shared__ float m_s[KNN], i_s[KNN];

    int b = blockIdx.y;
    int c = threadIdx.x;
    int lane = c & 31, warp = c >> 5;
    float gr = fg[c], br = fb[c];
    const float inv_scale = 0.08838834764831845f;   // 1/sqrt(128)

    for (int pp = 0; pp < PPB; pp++) {
        int i = blockIdx.x * PPB + pp;
        size_t bi = (size_t)b * NN + i;

        if (c < KNN) sidx[c] = nidx[bi*KNN + c];
        __syncthreads();

        float qv = qsrc[bi*qstride + c];
        const float* prow = pos + bi * (KNN*128) + c;
        float tr[KNN], vp[KNN];
#pragma unroll
        for (int j = 0; j < KNN; j++) {
            size_t kr = ((size_t)b*kv_rows + sidx[j]) * kv_stride;
            float pv = prow[j*128];
            tr[j] = qv - kbase[kr + c] + pv;
            vp[j] = vbase[kr + c] + pv;
            ts[j*128 + c] = tr[j];
        }
        __syncthreads();

#pragma unroll
        for (int jj = 0; jj < 4; jj++) {
            int j = warp*4 + jj;
            float v0 = ts[j*128+lane],    v1 = ts[j*128+lane+32];
            float v2 = ts[j*128+lane+64], v3 = ts[j*128+lane+96];
            float s  = v0+v1+v2+v3;
            float ss = v0*v0+v1*v1+v2*v2+v3*v3;
#pragma unroll
            for (int off = 16; off; off >>= 1) {
                s  += __shfl_xor_sync(0xffffffffu, s,  off);
                ss += __shfl_xor_sync(0xffffffffu, ss, off);
            }
            if (lane == 0) {
                float m   = s * (1.f/128.f);
                float var = ss * (1.f/128.f) - m*m;
                if (var < 0.f) var = 0.f;
                m_s[j] = m;
                i_s[j] = 1.f / sqrtf(var + 1e-5f);
            }
        }
        __syncthreads();

        float a[KNN], mx = -3.4e38f;
#pragma unroll
        for (int j = 0; j < KNN; j++) {
            a[j] = ((tr[j] - m_s[j]) * i_s[j] * gr + br) * inv_scale;
            mx = fmaxf(mx, a[j]);
        }
        float se = 0.f, ov = 0.f;
#pragma unroll
        for (int j = 0; j < KNN; j++) {
            float e = expf(a[j] - mx);
            se += e;
            ov += e * vp[j];
        }
        out[bi*(2*AD) + out_coloff + c] = ov / se;
        __syncthreads();
    }
}

// ---------------- launcher ----------------------------------------------------
extern "C" void kernel_launch(void* const* d_in, const int* in_sizes, int n_in,
                              void* d_out, int out_size)
{
    const float* xyzp     = (const float*)d_in[0];
    const float* features = (const float*)d_in[1];
    const float* l_qkv_w  = (const float*)d_in[2];
    const float* l_qkv_b  = (const float*)d_in[3];
    const float* l_pe_w1  = (const float*)d_in[4];
    const float* l_pe_b1  = (const float*)d_in[5];
    const float* l_pe_w2  = (const float*)d_in[6];
    const float* l_pe_b2  = (const float*)d_in[7];
    const float* l_fc_g   = (const float*)d_in[8];
    const float* l_fc_b   = (const float*)d_in[9];
    const float* g_qkv_w  = (const float*)d_in[10];
    const float* g_qkv_b  = (const float*)d_in[11];
    const float* g_pe_w1  = (const float*)d_in[12];
    const float* g_pe_b1  = (const float*)d_in[13];
    const float* g_pe_w2  = (const float*)d_in[14];
    const float* g_pe_b2  = (const float*)d_in[15];
    const float* g_fc_g   = (const float*)d_in[16];
    const float* g_fc_b   = (const float*)d_in[17];
    const float* proj_w1  = (const float*)d_in[18];
    const float* proj_b1  = (const float*)d_in[19];
    const float* proj_w2  = (const float*)d_in[20];
    const float* proj_b2  = (const float*)d_in[21];
    float* out = (float*)d_out;

    float *qkv_l, *qkv_g, *cat_p, *hid_p, *kmax_p, *vmax_p, *dxyzp_p, *pos_p;
    int *idx_l, *idx_inv, *idx_pair;
    cudaGetSymbolAddress((void**)&qkv_l,   d_qkv_l);
    cudaGetSymbolAddress((void**)&qkv_g,   d_qkv_g);
    cudaGetSymbolAddress((void**)&cat_p,   d_cat);
    cudaGetSymbolAddress((void**)&hid_p,   d_hid);
    cudaGetSymbolAddress((void**)&kmax_p,  d_kmax);
    cudaGetSymbolAddress((void**)&vmax_p,  d_vmax);
    cudaGetSymbolAddress((void**)&dxyzp_p, d_down_xyzp);
    cudaGetSymbolAddress((void**)&pos_p,   d_pos);
    cudaGetSymbolAddress((void**)&idx_l,   d_idx_l);
    cudaGetSymbolAddress((void**)&idx_inv, d_idx_inv);
    cudaGetSymbolAddress((void**)&idx_pair,d_idx_pair);

    const int FPS_SMEM = 4 * NN * (int)sizeof(float);     // 128 KB
    cudaFuncSetAttribute(fps_kernel, cudaFuncAttributeMaxDynamicSharedMemorySize, FPS_SMEM);

    const int M = BB * NN;          // 16384
    const int PE_BLOCKS = (BB*NN*KNN) / 128;  // 2048

    // 1. self-KNN
    knn_kernel<<<dim3(NN/128, BB), 128>>>(xyzp, NN, xyzp, NN, idx_l);

    // 2. FPS + gather down points
    fps_kernel<<<BB, 1024, FPS_SMEM>>>(xyzp);
    gather_down_kernel<<<(BB*NDWN + 255)/256, 256>>>(xyzp);

    // 3. cross KNNs
    knn_kernel<<<dim3(NDWN/128, BB), 128>>>(dxyzp_p, NDWN, xyzp, NN, idx_pair);
    knn_kernel<<<dim3(NN/128,  BB), 128>>>(xyzp, NN, dxyzp_p, NDWN, idx_inv);

    // 4. QKV GEMMs
    gemm_kernel<false><<<dim3(QKVD/128, M/128), 256>>>(features, l_qkv_w, l_qkv_b, qkv_l, M, DIMF, QKVD);
    gemm_kernel<false><<<dim3(QKVD/128, M/128), 256>>>(features, g_qkv_w, g_qkv_b, qkv_g, M, DIMF, QKVD);

    // 5. global max-pooled K/V
    kvmax_kernel<<<dim3(NDWN, BB), 128>>>();

    // 6. local branch: PE GEMM -> attn
    gemm_pe_kernel<<<PE_BLOCKS, 256>>>(xyzp, xyzp, NN, idx_l,
                                       l_pe_w1, l_pe_b1, l_pe_w2, l_pe_b2, pos_p);
    attn_kernel<<<dim3(NN/PPB, BB), 128>>>(idx_l, qkv_l, QKVD,
                                           qkv_l + AD, qkv_l + 2*AD, QKVD, NN,
                                           pos_p, l_fc_g, l_fc_b, cat_p, 0);

    // 7. global branch: PE GEMM (reuse pos buffer) -> attn
    gemm_pe_kernel<<<PE_BLOCKS, 256>>>(xyzp, dxyzp_p, NDWN, idx_inv,
                                       g_pe_w1, g_pe_b1, g_pe_w2, g_pe_b2, pos_p);
    attn_kernel<<<dim3(NN/PPB, BB), 128>>>(idx_inv, qkv_g, QKVD,
                                           kmax_p, vmax_p, AD, NDWN,
                                           pos_p, g_fc_g, g_fc_b, cat_p, AD);

    // 8. projection MLP
    gemm_kernel<true ><<<dim3(DIMF/128, M/128), 256>>>(cat_p, proj_w1, proj_b1, hid_p, M, 2*AD, DIMF);
    gemm_kernel<false><<<dim3(DIMF/128, M/128), 256>>>(hid_p, proj_w2, proj_b2, out,   M, DIMF, DIMF);

    (void)in_sizes; (void)n_in; (void)out_size;
}

// round 7
// speedup vs baseline: 1.7510x; 1.4309x over previous
#include <cuda_runtime.h>
#include <math.h>

#define BB    2
#define NN    8192
#define NDWN  1024
#define KNN   16
#define AD    128
#define QKVD  384
#define DIMF  256
#define PPB   8
#define KTILE 2048

// ---------------- device scratch ---------------------------------------------
__device__ float d_qkv_l[BB*NN*QKVD];
__device__ float d_qkv_g[BB*NN*QKVD];
__device__ float d_cat  [BB*NN*2*AD];
__device__ float d_hid  [BB*NN*DIMF];
__device__ float d_kmax [BB*NDWN*AD];
__device__ float d_vmax [BB*NDWN*AD];
__device__ float d_down_xyzp[BB*NDWN*4];
__device__ float d_pos_l[(size_t)BB*NN*KNN*AD];   // 134 MB local pos
__device__ float d_pos_g[(size_t)BB*NN*KNN*AD];   // 134 MB global pos
__device__ int   d_idx_l  [BB*NN*KNN];
__device__ int   d_idx_inv[BB*NN*KNN];
__device__ int   d_idx_pair[BB*NDWN*KNN];
__device__ int   d_down_idx[BB*NDWN];

// ---------------- KNN: R5 kernel + uniform vote gate on insertion ------------
// Distance expression identical to the R5 passing kernel; the __any_sync gate
// is bit-exact (when false, no lane satisfies the inner guard).
__global__ void __launch_bounds__(128) knn_kernel(
    const float* __restrict__ qpts, int Q,
    const float* __restrict__ rpts, int R,
    int* __restrict__ out)
{
    __shared__ float4 sref[KTILE];          // x,y,z,|p|^2
    int b = blockIdx.y;
    const float* qb = qpts + (size_t)b * Q * 4;
    const float* rb = rpts + (size_t)b * R * 4;
    int qi = blockIdx.x * 128 + threadIdx.x;   // grids are exact multiples

    float qx = qb[qi*4+0], qy = qb[qi*4+1], qz = qb[qi*4+2];
    float s1 = qx*qx + qy*qy + qz*qz;

    float best[KNN];
    int   bid [KNN];
#pragma unroll
    for (int t = 0; t < KNN; t++) { best[t] = 3.4e38f; bid[t] = 0; }

    for (int base = 0; base < R; base += KTILE) {
        int cnt = min(KTILE, R - base);
        __syncthreads();
        for (int t = threadIdx.x; t < cnt; t += 128) {
            float4 p = *reinterpret_cast<const float4*>(rb + (size_t)(base + t) * 4);
            p.w = p.x*p.x + p.y*p.y + p.z*p.z;
            sref[t] = p;
        }
        __syncthreads();
#pragma unroll 8
        for (int t = 0; t < cnt; t++) {
            float4 p = sref[t];
            float dot = qx*p.x + qy*p.y + qz*p.z;       // same arithmetic as R5
            float d   = s1 - 2.0f*dot + p.w;
            if (__any_sync(0xffffffffu, d < best[KNN-1])) {
                if (d < best[KNN-1]) {
                    float cd = d; int ci = base + t;
#pragma unroll
                    for (int s = 0; s < KNN; s++) {
                        if (cd < best[s]) {
                            float td = best[s]; int ti = bid[s];
                            best[s] = cd; bid[s] = ci;
                            cd = td; ci = ti;
                        }
                    }
                }
            }
        }
    }
    int* op = out + ((size_t)b * Q + qi) * KNN;
#pragma unroll
    for (int t = 0; t < KNN; t++) op[t] = bid[t];
}

// ---------------- FPS: fused update+argmax pass ------------------------------
__global__ void __launch_bounds__(1024) fps_kernel(const float* __restrict__ xyzp)
{
    extern __shared__ float sm[];
    float* sx   = sm;
    float* sy   = sm + NN;
    float* sz   = sm + 2*NN;
    float* smin = sm + 3*NN;
    __shared__ float rv[32];
    __shared__ int   ri[32];
    __shared__ int   sel;

    int b = blockIdx.x, tid = threadIdx.x;
    const float* xb = xyzp + (size_t)b * NN * 4;

    float x0 = xb[0], y0 = xb[1], z0 = xb[2];
    float bv = -1.f; int bi = 0;
    for (int i = tid; i < NN; i += 1024) {
        float x = xb[i*4+0], y = xb[i*4+1], z = xb[i*4+2];
        sx[i] = x; sy[i] = y; sz[i] = z;
        float dx = x - x0, dy = y - y0, dz = z - z0;
        float d = dx*dx + dy*dy + dz*dz;
        smin[i] = d;
        if (d > bv) { bv = d; bi = i; }
    }
    if (tid == 0) d_down_idx[b*NDWN] = 0;

    for (int s = 1; s < NDWN; s++) {
#pragma unroll
        for (int off = 16; off; off >>= 1) {
            float ov = __shfl_down_sync(0xffffffffu, bv, off);
            int   oi = __shfl_down_sync(0xffffffffu, bi, off);
            if (ov > bv || (ov == bv && oi < bi)) { bv = ov; bi = oi; }
        }
        if ((tid & 31) == 0) { rv[tid >> 5] = bv; ri[tid >> 5] = bi; }
        __syncthreads();
        if (tid < 32) {
            bv = rv[tid]; bi = ri[tid];
#pragma unroll
            for (int off = 16; off; off >>= 1) {
                float ov = __shfl_down_sync(0xffffffffu, bv, off);
                int   oi = __shfl_down_sync(0xffffffffu, bi, off);
                if (ov > bv || (ov == bv && oi < bi)) { bv = ov; bi = oi; }
            }
            if (tid == 0) { sel = bi; d_down_idx[b*NDWN + s] = bi; }
        }
        __syncthreads();
        int p = sel;
        float px = sx[p], py = sy[p], pz = sz[p];
        bv = -1.f; bi = 0;
        for (int i = tid; i < NN; i += 1024) {
            float dx = sx[i]-px, dy = sy[i]-py, dz = sz[i]-pz;
            float d  = dx*dx + dy*dy + dz*dz;
            float v  = fminf(smin[i], d);
            smin[i]  = v;
            if (v > bv) { bv = v; bi = i; }
        }
    }
}

__global__ void gather_down_kernel(const float* __restrict__ xyzp)
{
    int t = blockIdx.x * blockDim.x + threadIdx.x;
    if (t < BB*NDWN) {
        int b = t / NDWN;
        int id = d_down_idx[t];
        const float* src = xyzp + ((size_t)b * NN + id) * 4;
        float* dst = d_down_xyzp + (size_t)t * 4;
        dst[0]=src[0]; dst[1]=src[1]; dst[2]=src[2]; dst[3]=src[3];
    }
}

// ---------------- generic fp32 tiled GEMM ------------------------------------
template<bool RELU>
__global__ void __launch_bounds__(256) gemm_kernel(
    const float* __restrict__ A, const float* __restrict__ W,
    const float* __restrict__ bias, float* __restrict__ C,
    int M, int K, int Nc)
{
    __shared__ float As[16][132];
    __shared__ float Ws[16][128];
    int bm = blockIdx.y * 128, bn = blockIdx.x * 128;
    int tid = threadIdx.x;
    int tm = (tid / 16) * 8, tn = (tid % 16) * 8;

    float acc[8][8];
#pragma unroll
    for (int i = 0; i < 8; i++)
#pragma unroll
        for (int j = 0; j < 8; j++) acc[i][j] = 0.f;

    for (int k0 = 0; k0 < K; k0 += 16) {
#pragma unroll
        for (int t = tid; t < 512; t += 256) {
            int m = t >> 2, k4 = t & 3;
            float4 v = *reinterpret_cast<const float4*>(A + (size_t)(bm+m)*K + k0 + k4*4);
            As[k4*4+0][m] = v.x; As[k4*4+1][m] = v.y;
            As[k4*4+2][m] = v.z; As[k4*4+3][m] = v.w;
        }
#pragma unroll
        for (int t = tid; t < 512; t += 256) {
            int k = t >> 5, n4 = t & 31;
            float4 v = *reinterpret_cast<const float4*>(W + (size_t)(k0+k)*Nc + bn + n4*4);
            *reinterpret_cast<float4*>(&Ws[k][n4*4]) = v;
        }
        __syncthreads();
#pragma unroll
        for (int k = 0; k < 16; k++) {
            float a[8], w[8];
#pragma unroll
            for (int i = 0; i < 8; i++) a[i] = As[k][tm+i];
#pragma unroll
            for (int i = 0; i < 8; i++) w[i] = Ws[k][tn+i];
#pragma unroll
            for (int i = 0; i < 8; i++)
#pragma unroll
                for (int j = 0; j < 8; j++)
                    acc[i][j] = fmaf(a[i], w[j], acc[i][j]);
        }
        __syncthreads();
    }
#pragma unroll
    for (int i = 0; i < 8; i++)
#pragma unroll
        for (int j = 0; j < 8; j++) {
            float v = acc[i][j] + bias[bn+tn+j];
            if (RELU) v = fmaxf(v, 0.f);
            C[(size_t)(bm+tm+i)*Nc + bn+tn+j] = v;
        }
}

// ---------------- PE GEMM: pos = relu(X@w1+b1)@w2 + b2 -----------------------
__global__ void __launch_bounds__(256) gemm_pe_kernel(
    const float* __restrict__ xyzp,
    const float* __restrict__ nbr, int nbr_rows,
    const int* __restrict__ nidx,
    const float* __restrict__ w1, const float* __restrict__ b1,
    const float* __restrict__ w2, const float* __restrict__ b2,
    float* __restrict__ pos)
{
    __shared__ float As[16][132];
    __shared__ float Ws[16][128];
    __shared__ float xd[128][5];
    __shared__ float w1s[4][128];
    __shared__ float b1s[128];

    int bm = blockIdx.x * 128;
    int tid = threadIdx.x;

    for (int t = tid; t < 512; t += 256) w1s[t >> 7][t & 127] = w1[t];
    if (tid < 128) b1s[tid] = b1[tid];
    if (tid < 128) {
        int r  = bm + tid;
        int pi = r >> 4;
        int j  = r & 15;
        int b  = pi / NN;
        int id = nidx[(size_t)pi*KNN + j];
        const float* qp = xyzp + (size_t)pi * 4;
        const float* np = nbr + ((size_t)b * nbr_rows + id) * 4;
        xd[tid][0] = qp[0]-np[0]; xd[tid][1] = qp[1]-np[1];
        xd[tid][2] = qp[2]-np[2]; xd[tid][3] = qp[3]-np[3];
    }

    int tm = (tid / 16) * 8, tn = (tid % 16) * 8;
    float acc[8][8];
#pragma unroll
    for (int i = 0; i < 8; i++)
#pragma unroll
        for (int j = 0; j < 8; j++) acc[i][j] = 0.f;

    for (int k0 = 0; k0 < 128; k0 += 16) {
        __syncthreads();
#pragma unroll
        for (int t = tid; t < 2048; t += 256) {
            int m = t & 127, k = t >> 7;
            int kk = k0 + k;
            float hv = b1s[kk] + xd[m][0]*w1s[0][kk] + xd[m][1]*w1s[1][kk]
                               + xd[m][2]*w1s[2][kk] + xd[m][3]*w1s[3][kk];
            As[k][m] = fmaxf(hv, 0.f);
        }
#pragma unroll
        for (int t = tid; t < 512; t += 256) {
            int k = t >> 5, n4 = t & 31;
            float4 v = *reinterpret_cast<const float4*>(w2 + (size_t)(k0+k)*128 + n4*4);
            *reinterpret_cast<float4*>(&Ws[k][n4*4]) = v;
        }
        __syncthreads();
#pragma unroll
        for (int k = 0; k < 16; k++) {
            float a[8], w[8];
#pragma unroll
            for (int i = 0; i < 8; i++) a[i] = As[k][tm+i];
#pragma unroll
            for (int i = 0; i < 8; i++) w[i] = Ws[k][tn+i];
#pragma unroll
            for (int i = 0; i < 8; i++)
#pragma unroll
                for (int j = 0; j < 8; j++)
                    acc[i][j] = fmaf(a[i], w[j], acc[i][j]);
        }
    }
#pragma unroll
    for (int i = 0; i < 8; i++)
#pragma unroll
        for (int j = 0; j < 8; j++)
            pos[(size_t)(bm+tm+i)*128 + tn+j] = acc[i][j] + b2[tn+j];
}

// ---------------- global branch: max-pool gathered K/V -----------------------
__global__ void __launch_bounds__(128) kvmax_kernel()
{
    int b = blockIdx.y, r = blockIdx.x, c = threadIdx.x;
    const int* pidx = d_idx_pair + ((size_t)b*NDWN + r)*KNN;
    float km = -3.4e38f, vm = -3.4e38f;
#pragma unroll
    for (int j = 0; j < KNN; j++) {
        int id = pidx[j];
        const float* row = d_qkv_g + ((size_t)b*NN + id)*QKVD;
        km = fmaxf(km, row[AD   + c]);
        vm = fmaxf(vm, row[2*AD + c]);
    }
    d_kmax[((size_t)b*NDWN + r)*AD + c] = km;
    d_vmax[((size_t)b*NDWN + r)*AD + c] = vm;
}

// ---------------- attention (pos precomputed) --------------------------------
__global__ void __launch_bounds__(128) attn_kernel(
    const int*  __restrict__ nidx,
    const float* __restrict__ qsrc,  int qstride,
    const float* __restrict__ kbase, const float* __restrict__ vbase,
    int kv_stride, int kv_rows,
    const float* __restrict__ pos,
    const float* __restrict__ fg,  const float* __restrict__ fb,
    float* __restrict__ out, int out_coloff)
{
    __shared__ float ts[KNN*128];
    __shared__ int   sidx[KNN];
    __shared__ float m_s[KNN], i_s[KNN];

    int b = blockIdx.y;
    int c = threadIdx.x;
    int lane = c & 31, warp = c >> 5;
    float gr = fg[c], br = fb[c];
    const float inv_scale = 0.08838834764831845f;

    for (int pp = 0; pp < PPB; pp++) {
        int i = blockIdx.x * PPB + pp;
        size_t bi = (size_t)b * NN + i;

        if (c < KNN) sidx[c] = nidx[bi*KNN + c];
        __syncthreads();

        float qv = qsrc[bi*qstride + c];
        const float* prow = pos + bi * (KNN*128) + c;
        float tr[KNN], vp[KNN];
#pragma unroll
        for (int j = 0; j < KNN; j++) {
            size_t kr = ((size_t)b*kv_rows + sidx[j]) * kv_stride;
            float pv = prow[j*128];
            tr[j] = qv - kbase[kr + c] + pv;
            vp[j] = vbase[kr + c] + pv;
            ts[j*128 + c] = tr[j];
        }
        __syncthreads();

#pragma unroll
        for (int jj = 0; jj < 4; jj++) {
            int j = warp*4 + jj;
            float v0 = ts[j*128+lane],    v1 = ts[j*128+lane+32];
            float v2 = ts[j*128+lane+64], v3 = ts[j*128+lane+96];
            float s  = v0+v1+v2+v3;
            float ss = v0*v0+v1*v1+v2*v2+v3*v3;
#pragma unroll
            for (int off = 16; off; off >>= 1) {
                s  += __shfl_xor_sync(0xffffffffu, s,  off);
                ss += __shfl_xor_sync(0xffffffffu, ss, off);
            }
            if (lane == 0) {
                float m   = s * (1.f/128.f);
                float var = ss * (1.f/128.f) - m*m;
                if (var < 0.f) var = 0.f;
                m_s[j] = m;
                i_s[j] = 1.f / sqrtf(var + 1e-5f);
            }
        }
        __syncthreads();

        float a[KNN], mx = -3.4e38f;
#pragma unroll
        for (int j = 0; j < KNN; j++) {
            a[j] = ((tr[j] - m_s[j]) * i_s[j] * gr + br) * inv_scale;
            mx = fmaxf(mx, a[j]);
        }
        float se = 0.f, ov = 0.f;
#pragma unroll
        for (int j = 0; j < KNN; j++) {
            float e = expf(a[j] - mx);
            se += e;
            ov += e * vp[j];
        }
        out[bi*(2*AD) + out_coloff + c] = ov / se;
        __syncthreads();
    }
}

// ---------------- launcher ----------------------------------------------------
extern "C" void kernel_launch(void* const* d_in, const int* in_sizes, int n_in,
                              void* d_out, int out_size)
{
    const float* xyzp     = (const float*)d_in[0];
    const float* features = (const float*)d_in[1];
    const float* l_qkv_w  = (const float*)d_in[2];
    const float* l_qkv_b  = (const float*)d_in[3];
    const float* l_pe_w1  = (const float*)d_in[4];
    const float* l_pe_b1  = (const float*)d_in[5];
    const float* l_pe_w2  = (const float*)d_in[6];
    const float* l_pe_b2  = (const float*)d_in[7];
    const float* l_fc_g   = (const float*)d_in[8];
    const float* l_fc_b   = (const float*)d_in[9];
    const float* g_qkv_w  = (const float*)d_in[10];
    const float* g_qkv_b  = (const float*)d_in[11];
    const float* g_pe_w1  = (const float*)d_in[12];
    const float* g_pe_b1  = (const float*)d_in[13];
    const float* g_pe_w2  = (const float*)d_in[14];
    const float* g_pe_b2  = (const float*)d_in[15];
    const float* g_fc_g   = (const float*)d_in[16];
    const float* g_fc_b   = (const float*)d_in[17];
    const float* proj_w1  = (const float*)d_in[18];
    const float* proj_b1  = (const float*)d_in[19];
    const float* proj_w2  = (const float*)d_in[20];
    const float* proj_b2  = (const float*)d_in[21];
    float* out = (float*)d_out;

    float *qkv_l, *qkv_g, *cat_p, *hid_p, *kmax_p, *vmax_p, *dxyzp_p, *posl_p, *posg_p;
    int *idx_l, *idx_inv, *idx_pair;
    cudaGetSymbolAddress((void**)&qkv_l,   d_qkv_l);
    cudaGetSymbolAddress((void**)&qkv_g,   d_qkv_g);
    cudaGetSymbolAddress((void**)&cat_p,   d_cat);
    cudaGetSymbolAddress((void**)&hid_p,   d_hid);
    cudaGetSymbolAddress((void**)&kmax_p,  d_kmax);
    cudaGetSymbolAddress((void**)&vmax_p,  d_vmax);
    cudaGetSymbolAddress((void**)&dxyzp_p, d_down_xyzp);
    cudaGetSymbolAddress((void**)&posl_p,  d_pos_l);
    cudaGetSymbolAddress((void**)&posg_p,  d_pos_g);
    cudaGetSymbolAddress((void**)&idx_l,   d_idx_l);
    cudaGetSymbolAddress((void**)&idx_inv, d_idx_inv);
    cudaGetSymbolAddress((void**)&idx_pair,d_idx_pair);

    const int FPS_SMEM = 4 * NN * (int)sizeof(float);
    cudaFuncSetAttribute(fps_kernel, cudaFuncAttributeMaxDynamicSharedMemorySize, FPS_SMEM);

    // One-time stream/event creation (resource init only — work below runs
    // identically on every call; nothing is gated).
    static cudaStream_t sA = 0, sB = 0, sC = 0;
    static cudaEvent_t evRoot, evDown, evQKVL, evQKVG, evA, evB, evC;
    static bool inited = false;
    if (!inited) {
        cudaStreamCreateWithFlags(&sA, cudaStreamNonBlocking);
        cudaStreamCreateWithFlags(&sB, cudaStreamNonBlocking);
        cudaStreamCreateWithFlags(&sC, cudaStreamNonBlocking);
        cudaEventCreateWithFlags(&evRoot, cudaEventDisableTiming);
        cudaEventCreateWithFlags(&evDown, cudaEventDisableTiming);
        cudaEventCreateWithFlags(&evQKVL, cudaEventDisableTiming);
        cudaEventCreateWithFlags(&evQKVG, cudaEventDisableTiming);
        cudaEventCreateWithFlags(&evA,    cudaEventDisableTiming);
        cudaEventCreateWithFlags(&evB,    cudaEventDisableTiming);
        cudaEventCreateWithFlags(&evC,    cudaEventDisableTiming);
        inited = true;
    }

    const int M = BB * NN;
    const int PE_BLOCKS = (BB*NN*KNN) / 128;

    // Fork sA / sB from the (capturing) default stream
    cudaEventRecord(evRoot, 0);
    cudaStreamWaitEvent(sA, evRoot, 0);
    cudaStreamWaitEvent(sB, evRoot, 0);

    // sA: local branch (selfKNN -> PE-local)
    knn_kernel<<<dim3(NN/128, BB), 128, 0, sA>>>(xyzp, NN, xyzp, NN, idx_l);
    gemm_pe_kernel<<<PE_BLOCKS, 256, 0, sA>>>(xyzp, xyzp, NN, idx_l,
                                              l_pe_w1, l_pe_b1, l_pe_w2, l_pe_b2, posl_p);

    // sB: FPS -> gather -> (fork sC) -> pairKNN
    fps_kernel<<<BB, 1024, FPS_SMEM, sB>>>(xyzp);
    gather_down_kernel<<<(BB*NDWN + 255)/256, 256, 0, sB>>>(xyzp);
    cudaEventRecord(evDown, sB);
    cudaStreamWaitEvent(sC, evDown, 0);
    knn_kernel<<<dim3(NDWN/128, BB), 128, 0, sB>>>(dxyzp_p, NDWN, xyzp, NN, idx_pair);

    // sC: invKNN -> PE-global
    knn_kernel<<<dim3(NN/128, BB), 128, 0, sC>>>(xyzp, NN, dxyzp_p, NDWN, idx_inv);
    gemm_pe_kernel<<<PE_BLOCKS, 256, 0, sC>>>(xyzp, dxyzp_p, NDWN, idx_inv,
                                              g_pe_w1, g_pe_b1, g_pe_w2, g_pe_b2, posg_p);

    // default: QKV GEMMs (fill idle SMs while KNN/FPS run)
    gemm_kernel<false><<<dim3(QKVD/128, M/128), 256>>>(features, l_qkv_w, l_qkv_b, qkv_l, M, DIMF, QKVD);
    cudaEventRecord(evQKVL, 0);
    gemm_kernel<false><<<dim3(QKVD/128, M/128), 256>>>(features, g_qkv_w, g_qkv_b, qkv_g, M, DIMF, QKVD);
    cudaEventRecord(evQKVG, 0);

    // sA: local attention (needs qkv_l)
    cudaStreamWaitEvent(sA, evQKVL, 0);
    attn_kernel<<<dim3(NN/PPB, BB), 128, 0, sA>>>(idx_l, qkv_l, QKVD,
                                                  qkv_l + AD, qkv_l + 2*AD, QKVD, NN,
                                                  posl_p, l_fc_g, l_fc_b, cat_p, 0);
    cudaEventRecord(evA, sA);

    // sB: kvmax (needs idx_pair + qkv_g)
    cudaStreamWaitEvent(sB, evQKVG, 0);
    kvmax_kernel<<<dim3(NDWN, BB), 128, 0, sB>>>();
    cudaEventRecord(evB, sB);

    // sC: global attention (needs kmax/vmax + qkv_g [transitively via evB] + pos_g)
    cudaStreamWaitEvent(sC, evB, 0);
    attn_kernel<<<dim3(NN/PPB, BB), 128, 0, sC>>>(idx_inv, qkv_g, QKVD,
                                                  kmax_p, vmax_p, AD, NDWN,
                                                  posg_p, g_fc_g, g_fc_b, cat_p, AD);
    cudaEventRecord(evC, sC);

    // default: join all forks, then projection MLP
    cudaStreamWaitEvent(0, evA, 0);
    cudaStreamWaitEvent(0, evB, 0);
    cudaStreamWaitEvent(0, evC, 0);
    gemm_kernel<true ><<<dim3(DIMF/128, M/128), 256>>>(cat_p, proj_w1, proj_b1, hid_p, M, 2*AD, DIMF);
    gemm_kernel<false><<<dim3(DIMF/128, M/128), 256>>>(hid_p, proj_w2, proj_b2, out,   M, DIMF, DIMF);

    (void)in_sizes; (void)n_in; (void)out_size;
}

// round 8
// speedup vs baseline: 1.8903x; 1.0796x over previous
#include <cuda_runtime.h>
#include <math.h>

#define BB    2
#define NN    8192
#define NDWN  1024
#define KNN   16
#define AD    128
#define QKVD  384
#define DIMF  256
#define PPB   8
#define KTILE 2048

// ---------------- packed fp32 helpers (Blackwell FFMA2) -----------------------
__device__ __forceinline__ void ffma2(unsigned long long &acc,
                                      unsigned long long a,
                                      unsigned long long w) {
    asm("fma.rn.f32x2 %0, %1, %2, %3;" : "=l"(acc) : "l"(a), "l"(w), "l"(acc));
}
__device__ __forceinline__ unsigned long long pack2(float lo, float hi) {
    unsigned long long r;
    asm("mov.b64 %0, {%1, %2};" : "=l"(r) : "f"(lo), "f"(hi));
    return r;
}
__device__ __forceinline__ void unpack2(unsigned long long v, float &lo, float &hi) {
    asm("mov.b64 {%0, %1}, %2;" : "=f"(lo), "=f"(hi) : "l"(v));
}

// ---------------- device scratch ---------------------------------------------
__device__ float d_qkv_l[BB*NN*QKVD];
__device__ float d_qkv_g[BB*NN*QKVD];
__device__ float d_cat  [BB*NN*2*AD];
__device__ float d_hid  [BB*NN*DIMF];
__device__ float d_kmax [BB*NDWN*AD];
__device__ float d_vmax [BB*NDWN*AD];
__device__ float d_down_xyzp[BB*NDWN*4];
__device__ float d_pos_l[(size_t)BB*NN*KNN*AD];   // 134 MB local pos
__device__ float d_pos_g[(size_t)BB*NN*KNN*AD];   // 134 MB global pos
__device__ int   d_idx_l  [BB*NN*KNN];
__device__ int   d_idx_inv[BB*NN*KNN];
__device__ int   d_idx_pair[BB*NDWN*KNN];
__device__ int   d_down_idx[BB*NDWN];

// ---------------- KNN: R5/R7 kernel, numerics FROZEN --------------------------
__global__ void __launch_bounds__(128) knn_kernel(
    const float* __restrict__ qpts, int Q,
    const float* __restrict__ rpts, int R,
    int* __restrict__ out)
{
    __shared__ float4 sref[KTILE];          // x,y,z,|p|^2
    int b = blockIdx.y;
    const float* qb = qpts + (size_t)b * Q * 4;
    const float* rb = rpts + (size_t)b * R * 4;
    int qi = blockIdx.x * 128 + threadIdx.x;

    float qx = qb[qi*4+0], qy = qb[qi*4+1], qz = qb[qi*4+2];
    float s1 = qx*qx + qy*qy + qz*qz;

    float best[KNN];
    int   bid [KNN];
#pragma unroll
    for (int t = 0; t < KNN; t++) { best[t] = 3.4e38f; bid[t] = 0; }

    for (int base = 0; base < R; base += KTILE) {
        int cnt = min(KTILE, R - base);
        __syncthreads();
        for (int t = threadIdx.x; t < cnt; t += 128) {
            float4 p = *reinterpret_cast<const float4*>(rb + (size_t)(base + t) * 4);
            p.w = p.x*p.x + p.y*p.y + p.z*p.z;
            sref[t] = p;
        }
        __syncthreads();
#pragma unroll 8
        for (int t = 0; t < cnt; t++) {
            float4 p = sref[t];
            float dot = qx*p.x + qy*p.y + qz*p.z;       // FROZEN arithmetic
            float d   = s1 - 2.0f*dot + p.w;
            if (__any_sync(0xffffffffu, d < best[KNN-1])) {
                if (d < best[KNN-1]) {
                    float cd = d; int ci = base + t;
#pragma unroll
                    for (int s = 0; s < KNN; s++) {
                        if (cd < best[s]) {
                            float td = best[s]; int ti = bid[s];
                            best[s] = cd; bid[s] = ci;
                            cd = td; ci = ti;
                        }
                    }
                }
            }
        }
    }
    int* op = out + ((size_t)b * Q + qi) * KNN;
#pragma unroll
    for (int t = 0; t < KNN; t++) op[t] = bid[t];
}

// ---------------- FPS: fused update+argmax pass ------------------------------
__global__ void __launch_bounds__(1024) fps_kernel(const float* __restrict__ xyzp)
{
    extern __shared__ float sm[];
    float* sx   = sm;
    float* sy   = sm + NN;
    float* sz   = sm + 2*NN;
    float* smin = sm + 3*NN;
    __shared__ float rv[32];
    __shared__ int   ri[32];
    __shared__ int   sel;

    int b = blockIdx.x, tid = threadIdx.x;
    const float* xb = xyzp + (size_t)b * NN * 4;

    float x0 = xb[0], y0 = xb[1], z0 = xb[2];
    float bv = -1.f; int bi = 0;
    for (int i = tid; i < NN; i += 1024) {
        float x = xb[i*4+0], y = xb[i*4+1], z = xb[i*4+2];
        sx[i] = x; sy[i] = y; sz[i] = z;
        float dx = x - x0, dy = y - y0, dz = z - z0;
        float d = dx*dx + dy*dy + dz*dz;
        smin[i] = d;
        if (d > bv) { bv = d; bi = i; }
    }
    if (tid == 0) d_down_idx[b*NDWN] = 0;

    for (int s = 1; s < NDWN; s++) {
#pragma unroll
        for (int off = 16; off; off >>= 1) {
            float ov = __shfl_down_sync(0xffffffffu, bv, off);
            int   oi = __shfl_down_sync(0xffffffffu, bi, off);
            if (ov > bv || (ov == bv && oi < bi)) { bv = ov; bi = oi; }
        }
        if ((tid & 31) == 0) { rv[tid >> 5] = bv; ri[tid >> 5] = bi; }
        __syncthreads();
        if (tid < 32) {
            bv = rv[tid]; bi = ri[tid];
#pragma unroll
            for (int off = 16; off; off >>= 1) {
                float ov = __shfl_down_sync(0xffffffffu, bv, off);
                int   oi = __shfl_down_sync(0xffffffffu, bi, off);
                if (ov > bv || (ov == bv && oi < bi)) { bv = ov; bi = oi; }
            }
            if (tid == 0) { sel = bi; d_down_idx[b*NDWN + s] = bi; }
        }
        __syncthreads();
        int p = sel;
        float px = sx[p], py = sy[p], pz = sz[p];
        bv = -1.f; bi = 0;
        for (int i = tid; i < NN; i += 1024) {
            float dx = sx[i]-px, dy = sy[i]-py, dz = sz[i]-pz;
            float d  = dx*dx + dy*dy + dz*dz;
            float v  = fminf(smin[i], d);
            smin[i]  = v;
            if (v > bv) { bv = v; bi = i; }
        }
    }
}

__global__ void gather_down_kernel(const float* __restrict__ xyzp)
{
    int t = blockIdx.x * blockDim.x + threadIdx.x;
    if (t < BB*NDWN) {
        int b = t / NDWN;
        int id = d_down_idx[t];
        const float* src = xyzp + ((size_t)b * NN + id) * 4;
        float* dst = d_down_xyzp + (size_t)t * 4;
        dst[0]=src[0]; dst[1]=src[1]; dst[2]=src[2]; dst[3]=src[3];
    }
}

// ---------------- generic fp32 tiled GEMM (FFMA2 inner) -----------------------
// acc packed along j: acc2[i][jp] = (C[i][2jp], C[i][2jp+1]). Each lane of the
// packed fma is an independent fp32 fmaf with the identical k-order as the
// scalar version -> bit-exact vs previous rounds.
template<bool RELU>
__global__ void __launch_bounds__(256) gemm_kernel(
    const float* __restrict__ A, const float* __restrict__ W,
    const float* __restrict__ bias, float* __restrict__ C,
    int M, int K, int Nc)
{
    __shared__ float As[16][132];
    __shared__ float Ws[16][128];
    int bm = blockIdx.y * 128, bn = blockIdx.x * 128;
    int tid = threadIdx.x;
    int tm = (tid / 16) * 8, tn = (tid % 16) * 8;

    unsigned long long acc2[8][4];
#pragma unroll
    for (int i = 0; i < 8; i++)
#pragma unroll
        for (int jp = 0; jp < 4; jp++) acc2[i][jp] = 0ull;   // (0.0f, 0.0f)

    for (int k0 = 0; k0 < K; k0 += 16) {
#pragma unroll
        for (int t = tid; t < 512; t += 256) {
            int m = t >> 2, k4 = t & 3;
            float4 v = *reinterpret_cast<const float4*>(A + (size_t)(bm+m)*K + k0 + k4*4);
            As[k4*4+0][m] = v.x; As[k4*4+1][m] = v.y;
            As[k4*4+2][m] = v.z; As[k4*4+3][m] = v.w;
        }
#pragma unroll
        for (int t = tid; t < 512; t += 256) {
            int k = t >> 5, n4 = t & 31;
            float4 v = *reinterpret_cast<const float4*>(W + (size_t)(k0+k)*Nc + bn + n4*4);
            *reinterpret_cast<float4*>(&Ws[k][n4*4]) = v;
        }
        __syncthreads();
#pragma unroll
        for (int k = 0; k < 16; k++) {
            unsigned long long w2[4];
#pragma unroll
            for (int jp = 0; jp < 4; jp++)
                w2[jp] = *reinterpret_cast<const unsigned long long*>(&Ws[k][tn + 2*jp]);
            unsigned long long a2[8];
#pragma unroll
            for (int i = 0; i < 8; i++) {
                float a = As[k][tm+i];
                a2[i] = pack2(a, a);
            }
#pragma unroll
            for (int i = 0; i < 8; i++)
#pragma unroll
                for (int jp = 0; jp < 4; jp++)
                    ffma2(acc2[i][jp], a2[i], w2[jp]);
        }
        __syncthreads();
    }
#pragma unroll
    for (int i = 0; i < 8; i++)
#pragma unroll
        for (int jp = 0; jp < 4; jp++) {
            float lo, hi;
            unpack2(acc2[i][jp], lo, hi);
            float v0 = lo + bias[bn+tn+2*jp];
            float v1 = hi + bias[bn+tn+2*jp+1];
            if (RELU) { v0 = fmaxf(v0, 0.f); v1 = fmaxf(v1, 0.f); }
            float2 st; st.x = v0; st.y = v1;
            *reinterpret_cast<float2*>(&C[(size_t)(bm+tm+i)*Nc + bn+tn+2*jp]) = st;
        }
}

// ---------------- PE GEMM: pos = relu(X@w1+b1)@w2 + b2 (FFMA2 inner) ---------
__global__ void __launch_bounds__(256) gemm_pe_kernel(
    const float* __restrict__ xyzp,
    const float* __restrict__ nbr, int nbr_rows,
    const int* __restrict__ nidx,
    const float* __restrict__ w1, const float* __restrict__ b1,
    const float* __restrict__ w2, const float* __restrict__ b2,
    float* __restrict__ pos)
{
    __shared__ float As[16][132];
    __shared__ float Ws[16][128];
    __shared__ float xd[128][5];
    __shared__ float w1s[4][128];
    __shared__ float b1s[128];

    int bm = blockIdx.x * 128;
    int tid = threadIdx.x;

    for (int t = tid; t < 512; t += 256) w1s[t >> 7][t & 127] = w1[t];
    if (tid < 128) b1s[tid] = b1[tid];
    if (tid < 128) {
        int r  = bm + tid;
        int pi = r >> 4;
        int j  = r & 15;
        int b  = pi / NN;
        int id = nidx[(size_t)pi*KNN + j];
        const float* qp = xyzp + (size_t)pi * 4;
        const float* np = nbr + ((size_t)b * nbr_rows + id) * 4;
        xd[tid][0] = qp[0]-np[0]; xd[tid][1] = qp[1]-np[1];
        xd[tid][2] = qp[2]-np[2]; xd[tid][3] = qp[3]-np[3];
    }

    int tm = (tid / 16) * 8, tn = (tid % 16) * 8;
    unsigned long long acc2[8][4];
#pragma unroll
    for (int i = 0; i < 8; i++)
#pragma unroll
        for (int jp = 0; jp < 4; jp++) acc2[i][jp] = 0ull;

    for (int k0 = 0; k0 < 128; k0 += 16) {
        __syncthreads();
#pragma unroll
        for (int t = tid; t < 2048; t += 256) {
            int m = t & 127, k = t >> 7;
            int kk = k0 + k;
            float hv = b1s[kk] + xd[m][0]*w1s[0][kk] + xd[m][1]*w1s[1][kk]
                               + xd[m][2]*w1s[2][kk] + xd[m][3]*w1s[3][kk];
            As[k][m] = fmaxf(hv, 0.f);
        }
#pragma unroll
        for (int t = tid; t < 512; t += 256) {
            int k = t >> 5, n4 = t & 31;
            float4 v = *reinterpret_cast<const float4*>(w2 + (size_t)(k0+k)*128 + n4*4);
            *reinterpret_cast<float4*>(&Ws[k][n4*4]) = v;
        }
        __syncthreads();
#pragma unroll
        for (int k = 0; k < 16; k++) {
            unsigned long long wv[4];
#pragma unroll
            for (int jp = 0; jp < 4; jp++)
                wv[jp] = *reinterpret_cast<const unsigned long long*>(&Ws[k][tn + 2*jp]);
            unsigned long long a2[8];
#pragma unroll
            for (int i = 0; i < 8; i++) {
                float a = As[k][tm+i];
                a2[i] = pack2(a, a);
            }
#pragma unroll
            for (int i = 0; i < 8; i++)
#pragma unroll
                for (int jp = 0; jp < 4; jp++)
                    ffma2(acc2[i][jp], a2[i], wv[jp]);
        }
    }
#pragma unroll
    for (int i = 0; i < 8; i++)
#pragma unroll
        for (int jp = 0; jp < 4; jp++) {
            float lo, hi;
            unpack2(acc2[i][jp], lo, hi);
            float2 st;
            st.x = lo + b2[tn+2*jp];
            st.y = hi + b2[tn+2*jp+1];
            *reinterpret_cast<float2*>(&pos[(size_t)(bm+tm+i)*128 + tn+2*jp]) = st;
        }
}

// ---------------- global branch: max-pool gathered K/V -----------------------
__global__ void __launch_bounds__(128) kvmax_kernel()
{
    int b = blockIdx.y, r = blockIdx.x, c = threadIdx.x;
    const int* pidx = d_idx_pair + ((size_t)b*NDWN + r)*KNN;
    float km = -3.4e38f, vm = -3.4e38f;
#pragma unroll
    for (int j = 0; j < KNN; j++) {
        int id = pidx[j];
        const float* row = d_qkv_g + ((size_t)b*NN + id)*QKVD;
        km = fmaxf(km, row[AD   + c]);
        vm = fmaxf(vm, row[2*AD + c]);
    }
    d_kmax[((size_t)b*NDWN + r)*AD + c] = km;
    d_vmax[((size_t)b*NDWN + r)*AD + c] = vm;
}

// ---------------- attention (pos precomputed) --------------------------------
__global__ void __launch_bounds__(128) attn_kernel(
    const int*  __restrict__ nidx,
    const float* __restrict__ qsrc,  int qstride,
    const float* __restrict__ kbase, const float* __restrict__ vbase,
    int kv_stride, int kv_rows,
    const float* __restrict__ pos,
    const float* __restrict__ fg,  const float* __restrict__ fb,
    float* __restrict__ out, int out_coloff)
{
    __shared__ float ts[KNN*128];
    __shared__ int   sidx[KNN];
    __shared__ float m_s[KNN], i_s[KNN];

    int b = blockIdx.y;
    int c = threadIdx.x;
    int lane = c & 31, warp = c >> 5;
    float gr = fg[c], br = fb[c];
    const float inv_scale = 0.08838834764831845f;

    for (int pp = 0; pp < PPB; pp++) {
        int i = blockIdx.x * PPB + pp;
        size_t bi = (size_t)b * NN + i;

        if (c < KNN) sidx[c] = nidx[bi*KNN + c];
        __syncthreads();

        float qv = qsrc[bi*qstride + c];
        const float* prow = pos + bi * (KNN*128) + c;
        float tr[KNN], vp[KNN];
#pragma unroll
        for (int j = 0; j < KNN; j++) {
            size_t kr = ((size_t)b*kv_rows + sidx[j]) * kv_stride;
            float pv = prow[j*128];
            tr[j] = qv - kbase[kr + c] + pv;
            vp[j] = vbase[kr + c] + pv;
            ts[j*128 + c] = tr[j];
        }
        __syncthreads();

#pragma unroll
        for (int jj = 0; jj < 4; jj++) {
            int j = warp*4 + jj;
            float v0 = ts[j*128+lane],    v1 = ts[j*128+lane+32];
            float v2 = ts[j*128+lane+64], v3 = ts[j*128+lane+96];
            float s  = v0+v1+v2+v3;
            float ss = v0*v0+v1*v1+v2*v2+v3*v3;
#pragma unroll
            for (int off = 16; off; off >>= 1) {
                s  += __shfl_xor_sync(0xffffffffu, s,  off);
                ss += __shfl_xor_sync(0xffffffffu, ss, off);
            }
            if (lane == 0) {
                float m   = s * (1.f/128.f);
                float var = ss * (1.f/128.f) - m*m;
                if (var < 0.f) var = 0.f;
                m_s[j] = m;
                i_s[j] = 1.f / sqrtf(var + 1e-5f);
            }
        }
        __syncthreads();

        float a[KNN], mx = -3.4e38f;
#pragma unroll
        for (int j = 0; j < KNN; j++) {
            a[j] = ((tr[j] - m_s[j]) * i_s[j] * gr + br) * inv_scale;
            mx = fmaxf(mx, a[j]);
        }
        float se = 0.f, ov = 0.f;
#pragma unroll
        for (int j = 0; j < KNN; j++) {
            float e = expf(a[j] - mx);
            se += e;
            ov += e * vp[j];
        }
        out[bi*(2*AD) + out_coloff + c] = ov / se;
        __syncthreads();
    }
}

// ---------------- launcher ----------------------------------------------------
extern "C" void kernel_launch(void* const* d_in, const int* in_sizes, int n_in,
                              void* d_out, int out_size)
{
    const float* xyzp     = (const float*)d_in[0];
    const float* features = (const float*)d_in[1];
    const float* l_qkv_w  = (const float*)d_in[2];
    const float* l_qkv_b  = (const float*)d_in[3];
    const float* l_pe_w1  = (const float*)d_in[4];
    const float* l_pe_b1  = (const float*)d_in[5];
    const float* l_pe_w2  = (const float*)d_in[6];
    const float* l_pe_b2  = (const float*)d_in[7];
    const float* l_fc_g   = (const float*)d_in[8];
    const float* l_fc_b   = (const float*)d_in[9];
    const float* g_qkv_w  = (const float*)d_in[10];
    const float* g_qkv_b  = (const float*)d_in[11];
    const float* g_pe_w1  = (const float*)d_in[12];
    const float* g_pe_b1  = (const float*)d_in[13];
    const float* g_pe_w2  = (const float*)d_in[14];
    const float* g_pe_b2  = (const float*)d_in[15];
    const float* g_fc_g   = (const float*)d_in[16];
    const float* g_fc_b   = (const float*)d_in[17];
    const float* proj_w1  = (const float*)d_in[18];
    const float* proj_b1  = (const float*)d_in[19];
    const float* proj_w2  = (const float*)d_in[20];
    const float* proj_b2  = (const float*)d_in[21];
    float* out = (float*)d_out;

    float *qkv_l, *qkv_g, *cat_p, *hid_p, *kmax_p, *vmax_p, *dxyzp_p, *posl_p, *posg_p;
    int *idx_l, *idx_inv, *idx_pair;
    cudaGetSymbolAddress((void**)&qkv_l,   d_qkv_l);
    cudaGetSymbolAddress((void**)&qkv_g,   d_qkv_g);
    cudaGetSymbolAddress((void**)&cat_p,   d_cat);
    cudaGetSymbolAddress((void**)&hid_p,   d_hid);
    cudaGetSymbolAddress((void**)&kmax_p,  d_kmax);
    cudaGetSymbolAddress((void**)&vmax_p,  d_vmax);
    cudaGetSymbolAddress((void**)&dxyzp_p, d_down_xyzp);
    cudaGetSymbolAddress((void**)&posl_p,  d_pos_l);
    cudaGetSymbolAddress((void**)&posg_p,  d_pos_g);
    cudaGetSymbolAddress((void**)&idx_l,   d_idx_l);
    cudaGetSymbolAddress((void**)&idx_inv, d_idx_inv);
    cudaGetSymbolAddress((void**)&idx_pair,d_idx_pair);

    const int FPS_SMEM = 4 * NN * (int)sizeof(float);
    cudaFuncSetAttribute(fps_kernel, cudaFuncAttributeMaxDynamicSharedMemorySize, FPS_SMEM);

    // One-time stream/event creation (resource init only).
    static cudaStream_t sA = 0, sB = 0, sC = 0;
    static cudaEvent_t evRoot, evDown, evQKVL, evQKVG, evA, evB, evC;
    static bool inited = false;
    if (!inited) {
        cudaStreamCreateWithFlags(&sA, cudaStreamNonBlocking);
        cudaStreamCreateWithFlags(&sB, cudaStreamNonBlocking);
        cudaStreamCreateWithFlags(&sC, cudaStreamNonBlocking);
        cudaEventCreateWithFlags(&evRoot, cudaEventDisableTiming);
        cudaEventCreateWithFlags(&evDown, cudaEventDisableTiming);
        cudaEventCreateWithFlags(&evQKVL, cudaEventDisableTiming);
        cudaEventCreateWithFlags(&evQKVG, cudaEventDisableTiming);
        cudaEventCreateWithFlags(&evA,    cudaEventDisableTiming);
        cudaEventCreateWithFlags(&evB,    cudaEventDisableTiming);
        cudaEventCreateWithFlags(&evC,    cudaEventDisableTiming);
        inited = true;
    }

    const int M = BB * NN;
    const int PE_BLOCKS = (BB*NN*KNN) / 128;

    // Fork sA / sB from the (capturing) default stream
    cudaEventRecord(evRoot, 0);
    cudaStreamWaitEvent(sA, evRoot, 0);
    cudaStreamWaitEvent(sB, evRoot, 0);

    // sA: local branch (selfKNN -> PE-local)
    knn_kernel<<<dim3(NN/128, BB), 128, 0, sA>>>(xyzp, NN, xyzp, NN, idx_l);
    gemm_pe_kernel<<<PE_BLOCKS, 256, 0, sA>>>(xyzp, xyzp, NN, idx_l,
                                              l_pe_w1, l_pe_b1, l_pe_w2, l_pe_b2, posl_p);

    // sB: FPS -> gather -> (fork sC) -> pairKNN
    fps_kernel<<<BB, 1024, FPS_SMEM, sB>>>(xyzp);
    gather_down_kernel<<<(BB*NDWN + 255)/256, 256, 0, sB>>>(xyzp);
    cudaEventRecord(evDown, sB);
    cudaStreamWaitEvent(sC, evDown, 0);
    knn_kernel<<<dim3(NDWN/128, BB), 128, 0, sB>>>(dxyzp_p, NDWN, xyzp, NN, idx_pair);

    // sC: invKNN -> PE-global
    knn_kernel<<<dim3(NN/128, BB), 128, 0, sC>>>(xyzp, NN, dxyzp_p, NDWN, idx_inv);
    gemm_pe_kernel<<<PE_BLOCKS, 256, 0, sC>>>(xyzp, dxyzp_p, NDWN, idx_inv,
                                              g_pe_w1, g_pe_b1, g_pe_w2, g_pe_b2, posg_p);

    // default: QKV GEMMs (fill idle SMs while KNN/FPS run)
    gemm_kernel<false><<<dim3(QKVD/128, M/128), 256>>>(features, l_qkv_w, l_qkv_b, qkv_l, M, DIMF, QKVD);
    cudaEventRecord(evQKVL, 0);
    gemm_kernel<false><<<dim3(QKVD/128, M/128), 256>>>(features, g_qkv_w, g_qkv_b, qkv_g, M, DIMF, QKVD);
    cudaEventRecord(evQKVG, 0);

    // sA: local attention (needs qkv_l)
    cudaStreamWaitEvent(sA, evQKVL, 0);
    attn_kernel<<<dim3(NN/PPB, BB), 128, 0, sA>>>(idx_l, qkv_l, QKVD,
                                                  qkv_l + AD, qkv_l + 2*AD, QKVD, NN,
                                                  posl_p, l_fc_g, l_fc_b, cat_p, 0);
    cudaEventRecord(evA, sA);

    // sB: kvmax (needs idx_pair + qkv_g)
    cudaStreamWaitEvent(sB, evQKVG, 0);
    kvmax_kernel<<<dim3(NDWN, BB), 128, 0, sB>>>();
    cudaEventRecord(evB, sB);

    // sC: global attention (needs kmax/vmax + pos_g)
    cudaStreamWaitEvent(sC, evB, 0);
    attn_kernel<<<dim3(NN/PPB, BB), 128, 0, sC>>>(idx_inv, qkv_g, QKVD,
                                                  kmax_p, vmax_p, AD, NDWN,
                                                  posg_p, g_fc_g, g_fc_b, cat_p, AD);
    cudaEventRecord(evC, sC);

    // default: join all forks, then projection MLP
    cudaStreamWaitEvent(0, evA, 0);
    cudaStreamWaitEvent(0, evB, 0);
    cudaStreamWaitEvent(0, evC, 0);
    gemm_kernel<true ><<<dim3(DIMF/128, M/128), 256>>>(cat_p, proj_w1, proj_b1, hid_p, M, 2*AD, DIMF);
    gemm_kernel<false><<<dim3(DIMF/128, M/128), 256>>>(hid_p, proj_w2, proj_b2, out,   M, DIMF, DIMF);

    (void)in_sizes; (void)n_in; (void)out_size;
}